// round 15
// baseline (speedup 1.0000x reference)
#include <cuda_runtime.h>
#include <cstdint>
#include <math.h>

typedef unsigned long long u64;
typedef unsigned short u16;

// ---------------- problem constants ----------------
#define T_TOK 512
#define H_DIM 2048
#define N_EXP 32
#define N_GRP 8
#define TOPK_GRP 4
#define TOP_K 6
#define I_DIM 1408
#define I2_DIM 2816
#define NSI 2816
#define NSI2 5632
#define SCALE_F 2.5f
#define MAXM 512
#define NPAIR (T_TOK * TOP_K)   // 3072

// ---------------- scratch (static device memory; no allocation) ----------------
__device__ u16   g_xh[T_TOK * H_DIM];      // x hi fp16
__device__ u16   g_xl[T_TOK * H_DIM];      // x lo fp16
__device__ u16   g_A1h[NPAIR * I_DIM];     // routed act hi
__device__ u16   g_A1l[NPAIR * I_DIM];     // routed act lo
__device__ u16   g_ASh[T_TOK * NSI];       // shared act hi
__device__ u16   g_ASl[T_TOK * NSI];       // shared act lo
__device__ float g_EO[NPAIR * H_DIM];      // per-pair expert output
__device__ int   g_topk_ids[NPAIR];
__device__ float g_topk_w[NPAIR];
__device__ int   g_counts[N_EXP];
__device__ int   g_ex_tok[N_EXP * MAXM];
__device__ int   g_ex_pair[N_EXP * MAXM];

// ---------------- helpers ----------------
__device__ __forceinline__ uint32_t smem_u32(const void* p) {
    uint32_t a;
    asm("{ .reg .u64 t; cvta.to.shared.u64 t, %1; cvt.u32.u64 %0, t; }" : "=r"(a) : "l"(p));
    return a;
}
__device__ __forceinline__ uint32_t h2pack(float x0, float x1) {
    uint32_t r;
    asm("cvt.rn.f16x2.f32 %0, %1, %2;" : "=r"(r) : "f"(x1), "f"(x0));
    return r;
}
__device__ __forceinline__ uint32_t l2pack(float x0, float x1, uint32_t h) {
    float h0, h1;
    asm("{ .reg .f16 a, b; mov.b32 {a, b}, %2; cvt.f32.f16 %0, a; cvt.f32.f16 %1, b; }"
        : "=f"(h0), "=f"(h1) : "r"(h));
    return h2pack(x0 - h0, x1 - h1);
}

#define LDM_X4(r, a) \
    asm volatile("ldmatrix.sync.aligned.m8n8.x4.shared.b16 {%0,%1,%2,%3}, [%4];" \
        : "=r"((r)[0]), "=r"((r)[1]), "=r"((r)[2]), "=r"((r)[3]) : "r"(a))

#define MMA16816(d, a, b0v, b1v) \
    asm volatile("mma.sync.aligned.m16n8k16.row.col.f32.f16.f16.f32 " \
        "{%0,%1,%2,%3}, {%4,%5,%6,%7}, {%8,%9}, {%0,%1,%2,%3};" \
        : "+f"((d)[0]), "+f"((d)[1]), "+f"((d)[2]), "+f"((d)[3]) \
        : "r"((a)[0]), "r"((a)[1]), "r"((a)[2]), "r"((a)[3]), "r"(b0v), "r"(b1v))

#define STS128(addr, v) \
    asm volatile("st.shared.v4.b32 [%0], {%1, %2, %3, %4};" \
        :: "r"(addr), "r"((v).x), "r"((v).y), "r"((v).z), "r"((v).w) : "memory")

// smem layout (BK=16): row stride 48B, 128 rows per matrix
#define ROWB 48
#define OFF_AH 0
#define OFF_AL 6144
#define OFF_BH 12288
#define OFF_BL 18432
#define BUF_BYTES 24576
#define GEMM_SMEM (2 * BUF_BYTES)   // 48 KB -> 2 CTAs/SM

// convert 8 floats -> hi/lo f16x4 and store (weights / B side only)
__device__ __forceinline__ void cvt_store8(uint32_t sb_h, uint32_t sb_l, const float* f) {
    uint4 h, l;
    h.x = h2pack(f[0], f[1]); h.y = h2pack(f[2], f[3]);
    h.z = h2pack(f[4], f[5]); h.w = h2pack(f[6], f[7]);
    l.x = l2pack(f[0], f[1], h.x); l.y = l2pack(f[2], f[3], h.y);
    l.z = l2pack(f[4], f[5], h.z); l.w = l2pack(f[6], f[7], h.w);
    STS128(sb_h, h);
    STS128(sb_l, l);
}

// ---------------- x fp32 -> fp16 hi/lo pre-pass ----------------
__global__ void __launch_bounds__(256) cvt_x_kernel(
    const float* __restrict__ x, u16* __restrict__ xh, u16* __restrict__ xl, int n2)
{
    for (int i = blockIdx.x * blockDim.x + threadIdx.x; i < n2;
         i += gridDim.x * blockDim.x) {
        float v0 = x[2 * i], v1 = x[2 * i + 1];
        uint32_t h = h2pack(v0, v1);
        uint32_t l = l2pack(v0, v1, h);
        ((uint32_t*)xh)[i] = h;
        ((uint32_t*)xl)[i] = l;
    }
}

// =====================================================================
// Plain GEMM (down proj): C[rowsC[m]] = A[rowsA[m]] @ (B + e*strideB)
// A is fp16 hi/lo; B fp32 converted inline.
// CTA 128x128, BK=16, 8 warps (2x4), warp 64x32, fp16-split x3 HMMA.
// Padded m-rows are skipped at 16-row (mf) granularity — warp-uniform.
// =====================================================================
__global__ void __launch_bounds__(256, 2) wm_gemm_kernel(
    const u16* __restrict__ Ah, const u16* __restrict__ Al,
    const float* __restrict__ B, float* __restrict__ C,
    int Mfixed, const int* __restrict__ Mcnt,
    int nkt, int lda, int ldb, int ldc, size_t strideB,
    const int* __restrict__ rowsA, const int* __restrict__ rowsC)
{
    extern __shared__ char sm_raw[];
    int e = blockIdx.z;
    int M = Mcnt ? Mcnt[e] : Mfixed;
    int m0 = blockIdx.y * 128;
    if (m0 >= M) return;
    int n0 = blockIdx.x * 128;

    uint32_t smem0 = smem_u32(sm_raw);
    int tid = threadIdx.x;
    int wid = tid >> 5, lane = tid & 31;
    int wm = (wid >> 2) * 64, wn = (wid & 3) * 32;

    // rows active for this warp (uniform across warp); mf block live iff mf*16 < mlim
    int mlim = M - m0 - wm;
    int nmf = (mlim >= 64) ? 4 : ((mlim <= 0) ? 0 : ((mlim + 15) >> 4));

    // A producer: row = tid>>1, 8 halves at (tid&1)*8
    int prow = tid >> 1;
    int phalf = tid & 1;
    int mg = m0 + prow; if (mg > M - 1) mg = M - 1;
    int arow = rowsA ? rowsA[e * MAXM + mg] : mg;
    const u16* Ahp = Ah + (size_t)arow * lda + phalf * 8;
    const u16* Alp = Al + (size_t)arow * lda + phalf * 8;
    uint32_t aoff = (uint32_t)(prow * ROWB + phalf * 16);
    // B producer: n = tid&127, 8 k at (tid>>7)*8 (transpose into smem)
    int bn = tid & 127;
    int bkh = tid >> 7;
    const float* Bp = B + (size_t)e * strideB + (size_t)(bkh * 8) * ldb + n0 + bn;
    uint32_t boff = (uint32_t)(bn * ROWB + bkh * 16);

    uint32_t a_lm = (uint32_t)((wm + (lane & 15)) * ROWB + (lane >> 4) * 16);
    uint32_t b_lm = (uint32_t)((wn + (lane & 15)) * ROWB + (lane >> 4) * 16);

    float acc[4][4][4];
    #pragma unroll
    for (int i = 0; i < 4; i++)
        #pragma unroll
        for (int j = 0; j < 4; j++)
            #pragma unroll
            for (int q = 0; q < 4; q++) acc[i][j][q] = 0.f;

    uint4 arh, arl;
    float br[8];
    {
        arh = *(const uint4*)Ahp;
        arl = *(const uint4*)Alp;
        #pragma unroll
        for (int j = 0; j < 8; j++) br[j] = Bp[(size_t)j * ldb];
        STS128(smem0 + OFF_AH + aoff, arh);
        STS128(smem0 + OFF_AL + aoff, arl);
        cvt_store8(smem0 + OFF_BH + boff, smem0 + OFF_BL + boff, br);
    }
    __syncthreads();

    for (int kt = 0; kt < nkt; kt++) {
        int buf = kt & 1;
        bool more = (kt + 1 < nkt);
        if (more) {
            Ahp += 16; Alp += 16; Bp += (size_t)16 * ldb;
            arh = *(const uint4*)Ahp;
            arl = *(const uint4*)Alp;
            #pragma unroll
            for (int j = 0; j < 8; j++) br[j] = Bp[(size_t)j * ldb];
        }

        uint32_t base = smem0 + buf * BUF_BYTES;
        uint32_t ah[4][4];
        #pragma unroll
        for (int mf = 0; mf < 4; mf++)
            if (mf < nmf)
                LDM_X4(ah[mf], base + OFF_AH + a_lm + mf * (16 * ROWB));
        uint32_t bh[2][4], bl[2][4];
        #pragma unroll
        for (int nq = 0; nq < 2; nq++) {
            uint32_t bd = base + OFF_BH + b_lm + nq * (16 * ROWB);
            LDM_X4(bh[nq], bd);
            LDM_X4(bl[nq], bd + (OFF_BL - OFF_BH));
        }
        // p0: Ah*Bh ; p1: Ah*Bl  (16 independent accs between reuse)
        #pragma unroll
        for (int mf = 0; mf < 4; mf++)
            if (mf < nmf)
                #pragma unroll
                for (int nf = 0; nf < 4; nf++) {
                    int nq = nf >> 1, sel = nf & 1;
                    MMA16816(acc[mf][nf], ah[mf], bh[nq][sel], bh[nq][sel + 2]);
                }
        #pragma unroll
        for (int mf = 0; mf < 4; mf++)
            if (mf < nmf)
                #pragma unroll
                for (int nf = 0; nf < 4; nf++) {
                    int nq = nf >> 1, sel = nf & 1;
                    MMA16816(acc[mf][nf], ah[mf], bl[nq][sel], bl[nq][sel + 2]);
                }
        // p2: Al*Bh (load Al late to shorten live ranges)
        uint32_t al[4][4];
        #pragma unroll
        for (int mf = 0; mf < 4; mf++)
            if (mf < nmf)
                LDM_X4(al[mf], base + OFF_AL + a_lm + mf * (16 * ROWB));
        #pragma unroll
        for (int mf = 0; mf < 4; mf++)
            if (mf < nmf)
                #pragma unroll
                for (int nf = 0; nf < 4; nf++) {
                    int nq = nf >> 1, sel = nf & 1;
                    MMA16816(acc[mf][nf], al[mf], bh[nq][sel], bh[nq][sel + 2]);
                }

        if (more) {
            uint32_t sb = smem0 + (buf ^ 1) * BUF_BYTES;
            STS128(sb + OFF_AH + aoff, arh);
            STS128(sb + OFF_AL + aoff, arl);
            cvt_store8(sb + OFF_BH + boff, sb + OFF_BL + boff, br);
        }
        __syncthreads();
    }

    #pragma unroll
    for (int mf = 0; mf < 4; mf++) {
        int rbase = m0 + wm + mf * 16 + (lane >> 2);
        #pragma unroll
        for (int half = 0; half < 2; half++) {
            int mm = rbase + half * 8;
            if (mm < M) {
                int crow = rowsC ? rowsC[e * MAXM + mm] : mm;
                float* cp = C + (size_t)crow * ldc + n0 + wn + (lane & 3) * 2;
                #pragma unroll
                for (int nf = 0; nf < 4; nf++) {
                    float2 v;
                    v.x = acc[mf][nf][half * 2];
                    v.y = acc[mf][nf][half * 2 + 1];
                    *(float2*)(cp + nf * 8) = v;
                }
            }
        }
    }
}

// =====================================================================
// Fused gate/up GEMM + SiLU; A fp16 hi/lo in, ACT fp16 hi/lo out.
// CTA 128m x (64 gate + 64 up); warp 64m x 16n per half.
// Padded m-rows skipped at 16-row (mf) granularity — warp-uniform.
// =====================================================================
__global__ void __launch_bounds__(256, 2) fused_gu_kernel(
    const u16* __restrict__ Ah, const u16* __restrict__ Al,
    const float* __restrict__ B,
    u16* __restrict__ ACTh, u16* __restrict__ ACTl,
    int Mfixed, const int* __restrict__ Mcnt,
    int nkt, int lda, int ldb, int halfN, size_t strideB,
    const int* __restrict__ rowsA, const int* __restrict__ rowsC)
{
    extern __shared__ char sm_raw[];
    int e = blockIdx.z;
    int M = Mcnt ? Mcnt[e] : Mfixed;
    int m0 = blockIdx.y * 128;
    if (m0 >= M) return;
    int n0 = blockIdx.x * 64;

    uint32_t smem0 = smem_u32(sm_raw);
    int tid = threadIdx.x;
    int wid = tid >> 5, lane = tid & 31;
    int wm = (wid >> 2) * 64, wn = (wid & 3) * 16;

    int mlim = M - m0 - wm;
    int nmf = (mlim >= 64) ? 4 : ((mlim <= 0) ? 0 : ((mlim + 15) >> 4));

    int prow = tid >> 1;
    int phalf = tid & 1;
    int mg = m0 + prow; if (mg > M - 1) mg = M - 1;
    int arow = rowsA ? rowsA[e * MAXM + mg] : mg;
    const u16* Ahp = Ah + (size_t)arow * lda + phalf * 8;
    const u16* Alp = Al + (size_t)arow * lda + phalf * 8;
    uint32_t aoff = (uint32_t)(prow * ROWB + phalf * 16);
    // B producer: col = tid&127 (0-63 gate, 64-127 up), 8 k at (tid>>7)*8
    int col = tid & 127;
    int bkh = tid >> 7;
    int gcol = n0 + (col & 63) + (col >> 6) * halfN;
    const float* Bp = B + (size_t)e * strideB + (size_t)(bkh * 8) * ldb + gcol;
    uint32_t boff = (uint32_t)(col * ROWB + bkh * 16);

    uint32_t a_lm = (uint32_t)((wm + (lane & 15)) * ROWB + (lane >> 4) * 16);
    uint32_t b_lm0 = (uint32_t)((wn + (lane & 15)) * ROWB + (lane >> 4) * 16);

    float acc[4][2][2][4];
    #pragma unroll
    for (int i = 0; i < 4; i++)
        #pragma unroll
        for (int h = 0; h < 2; h++)
            #pragma unroll
            for (int j = 0; j < 2; j++)
                #pragma unroll
                for (int q = 0; q < 4; q++) acc[i][h][j][q] = 0.f;

    uint4 arh, arl;
    float br[8];
    {
        arh = *(const uint4*)Ahp;
        arl = *(const uint4*)Alp;
        #pragma unroll
        for (int j = 0; j < 8; j++) br[j] = Bp[(size_t)j * ldb];
        STS128(smem0 + OFF_AH + aoff, arh);
        STS128(smem0 + OFF_AL + aoff, arl);
        cvt_store8(smem0 + OFF_BH + boff, smem0 + OFF_BL + boff, br);
    }
    __syncthreads();

    for (int kt = 0; kt < nkt; kt++) {
        int buf = kt & 1;
        bool more = (kt + 1 < nkt);
        if (more) {
            Ahp += 16; Alp += 16; Bp += (size_t)16 * ldb;
            arh = *(const uint4*)Ahp;
            arl = *(const uint4*)Alp;
            #pragma unroll
            for (int j = 0; j < 8; j++) br[j] = Bp[(size_t)j * ldb];
        }

        uint32_t base = smem0 + buf * BUF_BYTES;
        uint32_t ah[4][4], al[4][4];
        #pragma unroll
        for (int mf = 0; mf < 4; mf++)
            if (mf < nmf) {
                uint32_t ad = base + OFF_AH + a_lm + mf * (16 * ROWB);
                LDM_X4(ah[mf], ad);
                LDM_X4(al[mf], ad + (OFF_AL - OFF_AH));
            }
        #pragma unroll
        for (int h = 0; h < 2; h++) {
            uint32_t bd = base + OFF_BH + b_lm0 + h * (64 * ROWB);
            uint32_t bh[4], bl[4];
            LDM_X4(bh, bd);
            LDM_X4(bl, bd + (OFF_BL - OFF_BH));
            #pragma unroll
            for (int mf = 0; mf < 4; mf++)
                if (mf < nmf)
                    #pragma unroll
                    for (int nf = 0; nf < 2; nf++)
                        MMA16816(acc[mf][h][nf], ah[mf], bh[nf], bh[nf + 2]);
            #pragma unroll
            for (int mf = 0; mf < 4; mf++)
                if (mf < nmf)
                    #pragma unroll
                    for (int nf = 0; nf < 2; nf++)
                        MMA16816(acc[mf][h][nf], ah[mf], bl[nf], bl[nf + 2]);
            #pragma unroll
            for (int mf = 0; mf < 4; mf++)
                if (mf < nmf)
                    #pragma unroll
                    for (int nf = 0; nf < 2; nf++)
                        MMA16816(acc[mf][h][nf], al[mf], bh[nf], bh[nf + 2]);
        }

        if (more) {
            uint32_t sb = smem0 + (buf ^ 1) * BUF_BYTES;
            STS128(sb + OFF_AH + aoff, arh);
            STS128(sb + OFF_AL + aoff, arl);
            cvt_store8(sb + OFF_BH + boff, sb + OFF_BL + boff, br);
        }
        __syncthreads();
    }

    // epilogue: act = silu(gate) * up -> fp16 hi/lo rows (gathered)
    #pragma unroll
    for (int mf = 0; mf < 4; mf++) {
        int rbase = m0 + wm + mf * 16 + (lane >> 2);
        #pragma unroll
        for (int half = 0; half < 2; half++) {
            int mm = rbase + half * 8;
            if (mm < M) {
                int crow = rowsC ? rowsC[e * MAXM + mm] : mm;
                size_t rowoff = (size_t)crow * halfN + n0 + wn + (lane & 3) * 2;
                #pragma unroll
                for (int nf = 0; nf < 2; nf++) {
                    float g0v = acc[mf][0][nf][half * 2];
                    float g1v = acc[mf][0][nf][half * 2 + 1];
                    float u0v = acc[mf][1][nf][half * 2];
                    float u1v = acc[mf][1][nf][half * 2 + 1];
                    float a0 = (g0v / (1.f + expf(-g0v))) * u0v;
                    float a1 = (g1v / (1.f + expf(-g1v))) * u1v;
                    uint32_t hx = h2pack(a0, a1);
                    uint32_t lx = l2pack(a0, a1, hx);
                    *(uint32_t*)(ACTh + rowoff + nf * 8) = hx;
                    *(uint32_t*)(ACTl + rowoff + nf * 8) = lx;
                }
            }
        }
    }
}

// ---------------- router: logits + sigmoid + grouped topk ----------------
__global__ void __launch_bounds__(256) router_kernel(
    const float* __restrict__ x, const float* __restrict__ gw,
    const float* __restrict__ bias, int* __restrict__ ids, float* __restrict__ tw)
{
    const unsigned FULL = 0xffffffffu;
    int warp = threadIdx.x >> 5, lane = threadIdx.x & 31;
    int t0 = (blockIdx.x * 8 + warp) * 4;
    const float* xr = x + (size_t)t0 * H_DIM;
    float b = bias[lane];

    float acc0 = 0.f, acc1 = 0.f, acc2 = 0.f, acc3 = 0.f;
    #pragma unroll 4
    for (int h = 0; h < H_DIM; h++) {
        float g = gw[h * N_EXP + lane];
        acc0 += xr[h] * g;
        acc1 += xr[H_DIM + h] * g;
        acc2 += xr[2 * H_DIM + h] * g;
        acc3 += xr[3 * H_DIM + h] * g;
    }
    float logits[4] = {acc0, acc1, acc2, acc3};

    for (int tt = 0; tt < 4; tt++) {
        int t = t0 + tt;
        float s   = 1.f / (1.f + expf(-logits[tt]));
        float sfc = s + b;

        float a  = sfc;
        float bb = __shfl_xor_sync(FULL, a, 1);
        float hi = fmaxf(a, bb), lo = fminf(a, bb);
        float hi2 = __shfl_xor_sync(FULL, hi, 2);
        float lo2 = __shfl_xor_sync(FULL, lo, 2);
        float top1   = fmaxf(hi, hi2);
        float second = fmaxf(fminf(hi, hi2), fmaxf(lo, lo2));
        float gscore = top1 + second;
        int gid = lane >> 2;

        int grank = 0;
        #pragma unroll
        for (int j = 0; j < N_GRP; j++) {
            float gj = __shfl_sync(FULL, gscore, j * 4);
            grank += (gj > gscore) || (gj == gscore && j < gid);
        }
        float masked = (grank < TOPK_GRP) ? sfc : -INFINITY;

        int rank = 0;
        #pragma unroll
        for (int j = 0; j < 32; j++) {
            float vj = __shfl_sync(FULL, masked, j);
            rank += (vj > masked) || (vj == masked && j < lane);
        }
        bool sel = rank < TOP_K;

        float wsum = sel ? s : 0.f;
        #pragma unroll
        for (int off = 16; off; off >>= 1) wsum += __shfl_xor_sync(FULL, wsum, off);

        if (sel) {
            ids[t * TOP_K + rank] = lane;
            tw[t * TOP_K + rank]  = s / wsum * SCALE_F;
        }
    }
}

// ---------------- deterministic expert->token compaction ----------------
__global__ void __launch_bounds__(1024) build_lists_kernel(
    const int* __restrict__ ids, int* __restrict__ counts,
    int* __restrict__ ex_tok, int* __restrict__ ex_pair)
{
    const unsigned FULL = 0xffffffffu;
    int e = threadIdx.x >> 5;
    int lane = threadIdx.x & 31;
    int t0 = lane * 16;

    int cnt = 0;
    for (int t = t0; t < t0 + 16; t++)
        #pragma unroll
        for (int k = 0; k < TOP_K; k++)
            if (ids[t * TOP_K + k] == e) cnt++;

    int off = cnt;
    #pragma unroll
    for (int d = 1; d < 32; d <<= 1) {
        int v = __shfl_up_sync(FULL, off, d);
        if (lane >= d) off += v;
    }
    int total = __shfl_sync(FULL, off, 31);
    off -= cnt;

    for (int t = t0; t < t0 + 16; t++)
        #pragma unroll
        for (int k = 0; k < TOP_K; k++)
            if (ids[t * TOP_K + k] == e) {
                ex_tok[e * MAXM + off]  = t;
                ex_pair[e * MAXM + off] = t * TOP_K + k;
                off++;
            }
    if (lane == 0) counts[e] = total;
}

// ---------------- combine: out[t] += sum_k w[t,k] * EO[t*6+k] ----------------
__global__ void __launch_bounds__(256) combine_kernel(
    const float* __restrict__ EO, const float* __restrict__ tw, float* __restrict__ out)
{
    int t = blockIdx.x;
    const float* w = tw + t * TOP_K;
    float w0 = w[0], w1 = w[1], w2v = w[2], w3 = w[3], w4 = w[4], w5 = w[5];
    const float* eb = EO + (size_t)t * TOP_K * H_DIM;
    float* orow = out + (size_t)t * H_DIM;
    for (int c = threadIdx.x; c < H_DIM; c += blockDim.x) {
        float v = orow[c];
        v += w0  * eb[c]
           + w1  * eb[H_DIM + c]
           + w2v * eb[2 * H_DIM + c]
           + w3  * eb[3 * H_DIM + c]
           + w4  * eb[4 * H_DIM + c]
           + w5  * eb[5 * H_DIM + c];
        orow[c] = v;
    }
}

// ---------------- launch ----------------
extern "C" void kernel_launch(void* const* d_in, const int* in_sizes, int n_in,
                              void* d_out, int out_size)
{
    (void)in_sizes; (void)n_in; (void)out_size;
    const float* x      = (const float*)d_in[0];
    const float* gate_w = (const float*)d_in[2];
    const float* cbias  = (const float*)d_in[3];
    const float* w13    = (const float*)d_in[4];
    const float* w2     = (const float*)d_in[5];
    const float* swgu   = (const float*)d_in[6];
    const float* swdn   = (const float*)d_in[7];
    float* out = (float*)d_out;

    float *pEO, *ptw;
    u16 *pxh, *pxl, *pA1h, *pA1l, *pASh, *pASl;
    int *pids, *pcnt, *ptok, *ppair;
    cudaGetSymbolAddress((void**)&pxh,  g_xh);
    cudaGetSymbolAddress((void**)&pxl,  g_xl);
    cudaGetSymbolAddress((void**)&pA1h, g_A1h);
    cudaGetSymbolAddress((void**)&pA1l, g_A1l);
    cudaGetSymbolAddress((void**)&pASh, g_ASh);
    cudaGetSymbolAddress((void**)&pASl, g_ASl);
    cudaGetSymbolAddress((void**)&pEO,  g_EO);
    cudaGetSymbolAddress((void**)&ptw,  g_topk_w);
    cudaGetSymbolAddress((void**)&pids, g_topk_ids);
    cudaGetSymbolAddress((void**)&pcnt, g_counts);
    cudaGetSymbolAddress((void**)&ptok, g_ex_tok);
    cudaGetSymbolAddress((void**)&ppair, g_ex_pair);

    cudaFuncSetAttribute(wm_gemm_kernel,
                         cudaFuncAttributeMaxDynamicSharedMemorySize, GEMM_SMEM);
    cudaFuncSetAttribute(fused_gu_kernel,
                         cudaFuncAttributeMaxDynamicSharedMemorySize, GEMM_SMEM);

    // 0) x -> fp16 hi/lo
    cvt_x_kernel<<<512, 256>>>(x, pxh, pxl, T_TOK * H_DIM / 2);
    // 1) router + topk
    router_kernel<<<16, 256>>>(x, gate_w, cbias, pids, ptw);
    // 2) deterministic per-expert lists
    build_lists_kernel<<<1, 1024>>>(pids, pcnt, ptok, ppair);
    // 3) routed gate/up + silu fused -> ACT1 (fp16 hi/lo)
    fused_gu_kernel<<<dim3(I_DIM / 64, 4, N_EXP), 256, GEMM_SMEM>>>(
        pxh, pxl, w13, pA1h, pA1l, 0, pcnt, H_DIM / 16, H_DIM, I2_DIM, I_DIM,
        (size_t)H_DIM * I2_DIM, ptok, ppair);
    // 4) routed down: EO[pair] = ACT1[pair] @ w2[e]
    wm_gemm_kernel<<<dim3(H_DIM / 128, 4, N_EXP), 256, GEMM_SMEM>>>(
        pA1h, pA1l, w2, pEO, 0, pcnt, I_DIM / 16, I_DIM, H_DIM, H_DIM,
        (size_t)I_DIM * H_DIM, ppair, ppair);
    // 5) shared gate/up + silu fused -> ACTS (fp16 hi/lo)
    fused_gu_kernel<<<dim3(NSI / 64, 4, 1), 256, GEMM_SMEM>>>(
        pxh, pxl, swgu, pASh, pASl, T_TOK, nullptr, H_DIM / 16, H_DIM, NSI2, NSI,
        0, nullptr, nullptr);
    // 6) shared down -> d_out (writes every element)
    wm_gemm_kernel<<<dim3(H_DIM / 128, 4, 1), 256, GEMM_SMEM>>>(
        pASh, pASl, swdn, out, T_TOK, nullptr, NSI / 16, NSI, H_DIM, H_DIM,
        0, nullptr, nullptr);
    // 7) out += weighted routed expert outputs (deterministic order)
    combine_kernel<<<T_TOK, 256>>>(pEO, ptw, out);
}

// round 16
// speedup vs baseline: 1.7578x; 1.7578x over previous
#include <cuda_runtime.h>
#include <cstdint>
#include <math.h>

typedef unsigned long long u64;
typedef unsigned short u16;

// ---------------- problem constants ----------------
#define T_TOK 512
#define H_DIM 2048
#define N_EXP 32
#define N_GRP 8
#define TOPK_GRP 4
#define TOP_K 6
#define I_DIM 1408
#define I2_DIM 2816
#define NSI 2816
#define NSI2 5632
#define SCALE_F 2.5f
#define MAXM 512
#define NPAIR (T_TOK * TOP_K)   // 3072

// ---------------- scratch (static device memory; no allocation) ----------------
__device__ u16   g_xh[T_TOK * H_DIM];      // x hi fp16
__device__ u16   g_xl[T_TOK * H_DIM];      // x lo fp16
__device__ u16   g_A1h[NPAIR * I_DIM];     // routed act hi
__device__ u16   g_A1l[NPAIR * I_DIM];     // routed act lo
__device__ u16   g_ASh[T_TOK * NSI];       // shared act hi
__device__ u16   g_ASl[T_TOK * NSI];       // shared act lo
__device__ float g_EO[NPAIR * H_DIM];      // per-pair expert output
__device__ int   g_topk_ids[NPAIR];
__device__ float g_topk_w[NPAIR];
__device__ int   g_counts[N_EXP];
__device__ int   g_ex_tok[N_EXP * MAXM];
__device__ int   g_ex_pair[N_EXP * MAXM];

// ---------------- helpers ----------------
__device__ __forceinline__ uint32_t smem_u32(const void* p) {
    uint32_t a;
    asm("{ .reg .u64 t; cvta.to.shared.u64 t, %1; cvt.u32.u64 %0, t; }" : "=r"(a) : "l"(p));
    return a;
}
__device__ __forceinline__ uint32_t h2pack(float x0, float x1) {
    uint32_t r;
    asm("cvt.rn.f16x2.f32 %0, %1, %2;" : "=r"(r) : "f"(x1), "f"(x0));
    return r;
}
__device__ __forceinline__ uint32_t l2pack(float x0, float x1, uint32_t h) {
    float h0, h1;
    asm("{ .reg .f16 a, b; mov.b32 {a, b}, %2; cvt.f32.f16 %0, a; cvt.f32.f16 %1, b; }"
        : "=f"(h0), "=f"(h1) : "r"(h));
    return h2pack(x0 - h0, x1 - h1);
}

#define LDM_X4(r, a) \
    asm volatile("ldmatrix.sync.aligned.m8n8.x4.shared.b16 {%0,%1,%2,%3}, [%4];" \
        : "=r"((r)[0]), "=r"((r)[1]), "=r"((r)[2]), "=r"((r)[3]) : "r"(a))

#define MMA16816(d, a, b0v, b1v) \
    asm volatile("mma.sync.aligned.m16n8k16.row.col.f32.f16.f16.f32 " \
        "{%0,%1,%2,%3}, {%4,%5,%6,%7}, {%8,%9}, {%0,%1,%2,%3};" \
        : "+f"((d)[0]), "+f"((d)[1]), "+f"((d)[2]), "+f"((d)[3]) \
        : "r"((a)[0]), "r"((a)[1]), "r"((a)[2]), "r"((a)[3]), "r"(b0v), "r"(b1v))

#define STS128(addr, v) \
    asm volatile("st.shared.v4.b32 [%0], {%1, %2, %3, %4};" \
        :: "r"(addr), "r"((v).x), "r"((v).y), "r"((v).z), "r"((v).w) : "memory")

// smem layout (BK=16): row stride 48B, 128 rows per matrix
#define ROWB 48
#define OFF_AH 0
#define OFF_AL 6144
#define OFF_BH 12288
#define OFF_BL 18432
#define BUF_BYTES 24576
#define GEMM_SMEM (2 * BUF_BYTES)   // 48 KB -> 2 CTAs/SM

// convert 8 floats -> hi/lo f16x4 and store (weights / B side only)
__device__ __forceinline__ void cvt_store8(uint32_t sb_h, uint32_t sb_l, const float* f) {
    uint4 h, l;
    h.x = h2pack(f[0], f[1]); h.y = h2pack(f[2], f[3]);
    h.z = h2pack(f[4], f[5]); h.w = h2pack(f[6], f[7]);
    l.x = l2pack(f[0], f[1], h.x); l.y = l2pack(f[2], f[3], h.y);
    l.z = l2pack(f[4], f[5], h.z); l.w = l2pack(f[6], f[7], h.w);
    STS128(sb_h, h);
    STS128(sb_l, l);
}

// ---------------- x fp32 -> fp16 hi/lo pre-pass ----------------
__global__ void __launch_bounds__(256) cvt_x_kernel(
    const float* __restrict__ x, u16* __restrict__ xh, u16* __restrict__ xl, int n2)
{
    for (int i = blockIdx.x * blockDim.x + threadIdx.x; i < n2;
         i += gridDim.x * blockDim.x) {
        float v0 = x[2 * i], v1 = x[2 * i + 1];
        uint32_t h = h2pack(v0, v1);
        uint32_t l = l2pack(v0, v1, h);
        ((uint32_t*)xh)[i] = h;
        ((uint32_t*)xl)[i] = l;
    }
}

// =====================================================================
// Plain GEMM (down proj): C[rowsC[m]] = A[rowsA[m]] @ (B + e*strideB)
// A is fp16 hi/lo; B fp32 converted inline.
// CTA 128x128, BK=16, 8 warps (2x4), warp 64x32, fp16-split x3 HMMA.
// =====================================================================
__global__ void __launch_bounds__(256, 2) wm_gemm_kernel(
    const u16* __restrict__ Ah, const u16* __restrict__ Al,
    const float* __restrict__ B, float* __restrict__ C,
    int Mfixed, const int* __restrict__ Mcnt,
    int nkt, int lda, int ldb, int ldc, size_t strideB,
    const int* __restrict__ rowsA, const int* __restrict__ rowsC)
{
    extern __shared__ char sm_raw[];
    int e = blockIdx.z;
    int M = Mcnt ? Mcnt[e] : Mfixed;
    int m0 = blockIdx.y * 128;
    if (m0 >= M) return;
    int n0 = blockIdx.x * 128;

    uint32_t smem0 = smem_u32(sm_raw);
    int tid = threadIdx.x;
    int wid = tid >> 5, lane = tid & 31;
    int wm = (wid >> 2) * 64, wn = (wid & 3) * 32;

    // A producer: row = tid>>1, 8 halves at (tid&1)*8
    int prow = tid >> 1;
    int phalf = tid & 1;
    int mg = m0 + prow; if (mg > M - 1) mg = M - 1;
    int arow = rowsA ? rowsA[e * MAXM + mg] : mg;
    const u16* Ahp = Ah + (size_t)arow * lda + phalf * 8;
    const u16* Alp = Al + (size_t)arow * lda + phalf * 8;
    uint32_t aoff = (uint32_t)(prow * ROWB + phalf * 16);
    // B producer: n = tid&127, 8 k at (tid>>7)*8 (transpose into smem)
    int bn = tid & 127;
    int bkh = tid >> 7;
    const float* Bp = B + (size_t)e * strideB + (size_t)(bkh * 8) * ldb + n0 + bn;
    uint32_t boff = (uint32_t)(bn * ROWB + bkh * 16);

    uint32_t a_lm = (uint32_t)((wm + (lane & 15)) * ROWB + (lane >> 4) * 16);
    uint32_t b_lm = (uint32_t)((wn + (lane & 15)) * ROWB + (lane >> 4) * 16);

    float acc[4][4][4];
    #pragma unroll
    for (int i = 0; i < 4; i++)
        #pragma unroll
        for (int j = 0; j < 4; j++)
            #pragma unroll
            for (int q = 0; q < 4; q++) acc[i][j][q] = 0.f;

    uint4 arh, arl;
    float br[8];
    {
        arh = *(const uint4*)Ahp;
        arl = *(const uint4*)Alp;
        #pragma unroll
        for (int j = 0; j < 8; j++) br[j] = Bp[(size_t)j * ldb];
        STS128(smem0 + OFF_AH + aoff, arh);
        STS128(smem0 + OFF_AL + aoff, arl);
        cvt_store8(smem0 + OFF_BH + boff, smem0 + OFF_BL + boff, br);
    }
    __syncthreads();

    for (int kt = 0; kt < nkt; kt++) {
        int buf = kt & 1;
        bool more = (kt + 1 < nkt);
        if (more) {
            Ahp += 16; Alp += 16; Bp += (size_t)16 * ldb;
            arh = *(const uint4*)Ahp;
            arl = *(const uint4*)Alp;
            #pragma unroll
            for (int j = 0; j < 8; j++) br[j] = Bp[(size_t)j * ldb];
        }

        uint32_t base = smem0 + buf * BUF_BYTES;
        uint32_t ah[4][4];
        #pragma unroll
        for (int mf = 0; mf < 4; mf++)
            LDM_X4(ah[mf], base + OFF_AH + a_lm + mf * (16 * ROWB));
        uint32_t bh[2][4], bl[2][4];
        #pragma unroll
        for (int nq = 0; nq < 2; nq++) {
            uint32_t bd = base + OFF_BH + b_lm + nq * (16 * ROWB);
            LDM_X4(bh[nq], bd);
            LDM_X4(bl[nq], bd + (OFF_BL - OFF_BH));
        }
        // p0: Ah*Bh ; p1: Ah*Bl  (16 independent accs between reuse)
        #pragma unroll
        for (int mf = 0; mf < 4; mf++)
            #pragma unroll
            for (int nf = 0; nf < 4; nf++) {
                int nq = nf >> 1, sel = nf & 1;
                MMA16816(acc[mf][nf], ah[mf], bh[nq][sel], bh[nq][sel + 2]);
            }
        #pragma unroll
        for (int mf = 0; mf < 4; mf++)
            #pragma unroll
            for (int nf = 0; nf < 4; nf++) {
                int nq = nf >> 1, sel = nf & 1;
                MMA16816(acc[mf][nf], ah[mf], bl[nq][sel], bl[nq][sel + 2]);
            }
        // p2: Al*Bh (load Al late to shorten live ranges)
        uint32_t al[4][4];
        #pragma unroll
        for (int mf = 0; mf < 4; mf++)
            LDM_X4(al[mf], base + OFF_AL + a_lm + mf * (16 * ROWB));
        #pragma unroll
        for (int mf = 0; mf < 4; mf++)
            #pragma unroll
            for (int nf = 0; nf < 4; nf++) {
                int nq = nf >> 1, sel = nf & 1;
                MMA16816(acc[mf][nf], al[mf], bh[nq][sel], bh[nq][sel + 2]);
            }

        if (more) {
            uint32_t sb = smem0 + (buf ^ 1) * BUF_BYTES;
            STS128(sb + OFF_AH + aoff, arh);
            STS128(sb + OFF_AL + aoff, arl);
            cvt_store8(sb + OFF_BH + boff, sb + OFF_BL + boff, br);
        }
        __syncthreads();
    }

    #pragma unroll
    for (int mf = 0; mf < 4; mf++) {
        int rbase = m0 + wm + mf * 16 + (lane >> 2);
        #pragma unroll
        for (int half = 0; half < 2; half++) {
            int mm = rbase + half * 8;
            if (mm < M) {
                int crow = rowsC ? rowsC[e * MAXM + mm] : mm;
                float* cp = C + (size_t)crow * ldc + n0 + wn + (lane & 3) * 2;
                #pragma unroll
                for (int nf = 0; nf < 4; nf++) {
                    float2 v;
                    v.x = acc[mf][nf][half * 2];
                    v.y = acc[mf][nf][half * 2 + 1];
                    *(float2*)(cp + nf * 8) = v;
                }
            }
        }
    }
}

// =====================================================================
// Fused gate/up GEMM + SiLU; A fp16 hi/lo in, ACT fp16 hi/lo out.
// CTA 128m x (64 gate + 64 up); warp 64m x 16n per half.
// =====================================================================
__global__ void __launch_bounds__(256, 2) fused_gu_kernel(
    const u16* __restrict__ Ah, const u16* __restrict__ Al,
    const float* __restrict__ B,
    u16* __restrict__ ACTh, u16* __restrict__ ACTl,
    int Mfixed, const int* __restrict__ Mcnt,
    int nkt, int lda, int ldb, int halfN, size_t strideB,
    const int* __restrict__ rowsA, const int* __restrict__ rowsC)
{
    extern __shared__ char sm_raw[];
    int e = blockIdx.z;
    int M = Mcnt ? Mcnt[e] : Mfixed;
    int m0 = blockIdx.y * 128;
    if (m0 >= M) return;
    int n0 = blockIdx.x * 64;

    uint32_t smem0 = smem_u32(sm_raw);
    int tid = threadIdx.x;
    int wid = tid >> 5, lane = tid & 31;
    int wm = (wid >> 2) * 64, wn = (wid & 3) * 16;

    int prow = tid >> 1;
    int phalf = tid & 1;
    int mg = m0 + prow; if (mg > M - 1) mg = M - 1;
    int arow = rowsA ? rowsA[e * MAXM + mg] : mg;
    const u16* Ahp = Ah + (size_t)arow * lda + phalf * 8;
    const u16* Alp = Al + (size_t)arow * lda + phalf * 8;
    uint32_t aoff = (uint32_t)(prow * ROWB + phalf * 16);
    // B producer: col = tid&127 (0-63 gate, 64-127 up), 8 k at (tid>>7)*8
    int col = tid & 127;
    int bkh = tid >> 7;
    int gcol = n0 + (col & 63) + (col >> 6) * halfN;
    const float* Bp = B + (size_t)e * strideB + (size_t)(bkh * 8) * ldb + gcol;
    uint32_t boff = (uint32_t)(col * ROWB + bkh * 16);

    uint32_t a_lm = (uint32_t)((wm + (lane & 15)) * ROWB + (lane >> 4) * 16);
    uint32_t b_lm0 = (uint32_t)((wn + (lane & 15)) * ROWB + (lane >> 4) * 16);

    float acc[4][2][2][4];
    #pragma unroll
    for (int i = 0; i < 4; i++)
        #pragma unroll
        for (int h = 0; h < 2; h++)
            #pragma unroll
            for (int j = 0; j < 2; j++)
                #pragma unroll
                for (int q = 0; q < 4; q++) acc[i][h][j][q] = 0.f;

    uint4 arh, arl;
    float br[8];
    {
        arh = *(const uint4*)Ahp;
        arl = *(const uint4*)Alp;
        #pragma unroll
        for (int j = 0; j < 8; j++) br[j] = Bp[(size_t)j * ldb];
        STS128(smem0 + OFF_AH + aoff, arh);
        STS128(smem0 + OFF_AL + aoff, arl);
        cvt_store8(smem0 + OFF_BH + boff, smem0 + OFF_BL + boff, br);
    }
    __syncthreads();

    for (int kt = 0; kt < nkt; kt++) {
        int buf = kt & 1;
        bool more = (kt + 1 < nkt);
        if (more) {
            Ahp += 16; Alp += 16; Bp += (size_t)16 * ldb;
            arh = *(const uint4*)Ahp;
            arl = *(const uint4*)Alp;
            #pragma unroll
            for (int j = 0; j < 8; j++) br[j] = Bp[(size_t)j * ldb];
        }

        uint32_t base = smem0 + buf * BUF_BYTES;
        uint32_t ah[4][4], al[4][4];
        #pragma unroll
        for (int mf = 0; mf < 4; mf++) {
            uint32_t ad = base + OFF_AH + a_lm + mf * (16 * ROWB);
            LDM_X4(ah[mf], ad);
            LDM_X4(al[mf], ad + (OFF_AL - OFF_AH));
        }
        #pragma unroll
        for (int h = 0; h < 2; h++) {
            uint32_t bd = base + OFF_BH + b_lm0 + h * (64 * ROWB);
            uint32_t bh[4], bl[4];
            LDM_X4(bh, bd);
            LDM_X4(bl, bd + (OFF_BL - OFF_BH));
            #pragma unroll
            for (int mf = 0; mf < 4; mf++)
                #pragma unroll
                for (int nf = 0; nf < 2; nf++)
                    MMA16816(acc[mf][h][nf], ah[mf], bh[nf], bh[nf + 2]);
            #pragma unroll
            for (int mf = 0; mf < 4; mf++)
                #pragma unroll
                for (int nf = 0; nf < 2; nf++)
                    MMA16816(acc[mf][h][nf], ah[mf], bl[nf], bl[nf + 2]);
            #pragma unroll
            for (int mf = 0; mf < 4; mf++)
                #pragma unroll
                for (int nf = 0; nf < 2; nf++)
                    MMA16816(acc[mf][h][nf], al[mf], bh[nf], bh[nf + 2]);
        }

        if (more) {
            uint32_t sb = smem0 + (buf ^ 1) * BUF_BYTES;
            STS128(sb + OFF_AH + aoff, arh);
            STS128(sb + OFF_AL + aoff, arl);
            cvt_store8(sb + OFF_BH + boff, sb + OFF_BL + boff, br);
        }
        __syncthreads();
    }

    // epilogue: act = silu(gate) * up -> fp16 hi/lo rows (gathered)
    #pragma unroll
    for (int mf = 0; mf < 4; mf++) {
        int rbase = m0 + wm + mf * 16 + (lane >> 2);
        #pragma unroll
        for (int half = 0; half < 2; half++) {
            int mm = rbase + half * 8;
            if (mm < M) {
                int crow = rowsC ? rowsC[e * MAXM + mm] : mm;
                size_t rowoff = (size_t)crow * halfN + n0 + wn + (lane & 3) * 2;
                #pragma unroll
                for (int nf = 0; nf < 2; nf++) {
                    float g0v = acc[mf][0][nf][half * 2];
                    float g1v = acc[mf][0][nf][half * 2 + 1];
                    float u0v = acc[mf][1][nf][half * 2];
                    float u1v = acc[mf][1][nf][half * 2 + 1];
                    float a0 = (g0v / (1.f + expf(-g0v))) * u0v;
                    float a1 = (g1v / (1.f + expf(-g1v))) * u1v;
                    uint32_t hx = h2pack(a0, a1);
                    uint32_t lx = l2pack(a0, a1, hx);
                    *(uint32_t*)(ACTh + rowoff + nf * 8) = hx;
                    *(uint32_t*)(ACTl + rowoff + nf * 8) = lx;
                }
            }
        }
    }
}

// ---------------- router: logits + sigmoid + grouped topk ----------------
__global__ void __launch_bounds__(256) router_kernel(
    const float* __restrict__ x, const float* __restrict__ gw,
    const float* __restrict__ bias, int* __restrict__ ids, float* __restrict__ tw)
{
    const unsigned FULL = 0xffffffffu;
    int warp = threadIdx.x >> 5, lane = threadIdx.x & 31;
    int t0 = (blockIdx.x * 8 + warp) * 4;
    const float* xr = x + (size_t)t0 * H_DIM;
    float b = bias[lane];

    float acc0 = 0.f, acc1 = 0.f, acc2 = 0.f, acc3 = 0.f;
    #pragma unroll 4
    for (int h = 0; h < H_DIM; h++) {
        float g = gw[h * N_EXP + lane];
        acc0 += xr[h] * g;
        acc1 += xr[H_DIM + h] * g;
        acc2 += xr[2 * H_DIM + h] * g;
        acc3 += xr[3 * H_DIM + h] * g;
    }
    float logits[4] = {acc0, acc1, acc2, acc3};

    for (int tt = 0; tt < 4; tt++) {
        int t = t0 + tt;
        float s   = 1.f / (1.f + expf(-logits[tt]));
        float sfc = s + b;

        float a  = sfc;
        float bb = __shfl_xor_sync(FULL, a, 1);
        float hi = fmaxf(a, bb), lo = fminf(a, bb);
        float hi2 = __shfl_xor_sync(FULL, hi, 2);
        float lo2 = __shfl_xor_sync(FULL, lo, 2);
        float top1   = fmaxf(hi, hi2);
        float second = fmaxf(fminf(hi, hi2), fmaxf(lo, lo2));
        float gscore = top1 + second;
        int gid = lane >> 2;

        int grank = 0;
        #pragma unroll
        for (int j = 0; j < N_GRP; j++) {
            float gj = __shfl_sync(FULL, gscore, j * 4);
            grank += (gj > gscore) || (gj == gscore && j < gid);
        }
        float masked = (grank < TOPK_GRP) ? sfc : -INFINITY;

        int rank = 0;
        #pragma unroll
        for (int j = 0; j < 32; j++) {
            float vj = __shfl_sync(FULL, masked, j);
            rank += (vj > masked) || (vj == masked && j < lane);
        }
        bool sel = rank < TOP_K;

        float wsum = sel ? s : 0.f;
        #pragma unroll
        for (int off = 16; off; off >>= 1) wsum += __shfl_xor_sync(FULL, wsum, off);

        if (sel) {
            ids[t * TOP_K + rank] = lane;
            tw[t * TOP_K + rank]  = s / wsum * SCALE_F;
        }
    }
}

// ---------------- deterministic expert->token compaction ----------------
__global__ void __launch_bounds__(1024) build_lists_kernel(
    const int* __restrict__ ids, int* __restrict__ counts,
    int* __restrict__ ex_tok, int* __restrict__ ex_pair)
{
    const unsigned FULL = 0xffffffffu;
    int e = threadIdx.x >> 5;
    int lane = threadIdx.x & 31;
    int t0 = lane * 16;

    int cnt = 0;
    for (int t = t0; t < t0 + 16; t++)
        #pragma unroll
        for (int k = 0; k < TOP_K; k++)
            if (ids[t * TOP_K + k] == e) cnt++;

    int off = cnt;
    #pragma unroll
    for (int d = 1; d < 32; d <<= 1) {
        int v = __shfl_up_sync(FULL, off, d);
        if (lane >= d) off += v;
    }
    int total = __shfl_sync(FULL, off, 31);
    off -= cnt;

    for (int t = t0; t < t0 + 16; t++)
        #pragma unroll
        for (int k = 0; k < TOP_K; k++)
            if (ids[t * TOP_K + k] == e) {
                ex_tok[e * MAXM + off]  = t;
                ex_pair[e * MAXM + off] = t * TOP_K + k;
                off++;
            }
    if (lane == 0) counts[e] = total;
}

// ---------------- combine: out[t] += sum_k w[t,k] * EO[t*6+k] ----------------
__global__ void __launch_bounds__(256) combine_kernel(
    const float* __restrict__ EO, const float* __restrict__ tw, float* __restrict__ out)
{
    int t = blockIdx.x;
    const float* w = tw + t * TOP_K;
    float w0 = w[0], w1 = w[1], w2v = w[2], w3 = w[3], w4 = w[4], w5 = w[5];
    const float* eb = EO + (size_t)t * TOP_K * H_DIM;
    float* orow = out + (size_t)t * H_DIM;
    for (int c = threadIdx.x; c < H_DIM; c += blockDim.x) {
        float v = orow[c];
        v += w0  * eb[c]
           + w1  * eb[H_DIM + c]
           + w2v * eb[2 * H_DIM + c]
           + w3  * eb[3 * H_DIM + c]
           + w4  * eb[4 * H_DIM + c]
           + w5  * eb[5 * H_DIM + c];
        orow[c] = v;
    }
}

// ---------------- launch (forked graph: shared chain || routed chain) ------
extern "C" void kernel_launch(void* const* d_in, const int* in_sizes, int n_in,
                              void* d_out, int out_size)
{
    (void)in_sizes; (void)n_in; (void)out_size;
    const float* x      = (const float*)d_in[0];
    const float* gate_w = (const float*)d_in[2];
    const float* cbias  = (const float*)d_in[3];
    const float* w13    = (const float*)d_in[4];
    const float* w2     = (const float*)d_in[5];
    const float* swgu   = (const float*)d_in[6];
    const float* swdn   = (const float*)d_in[7];
    float* out = (float*)d_out;

    float *pEO, *ptw;
    u16 *pxh, *pxl, *pA1h, *pA1l, *pASh, *pASl;
    int *pids, *pcnt, *ptok, *ppair;
    cudaGetSymbolAddress((void**)&pxh,  g_xh);
    cudaGetSymbolAddress((void**)&pxl,  g_xl);
    cudaGetSymbolAddress((void**)&pA1h, g_A1h);
    cudaGetSymbolAddress((void**)&pA1l, g_A1l);
    cudaGetSymbolAddress((void**)&pASh, g_ASh);
    cudaGetSymbolAddress((void**)&pASl, g_ASl);
    cudaGetSymbolAddress((void**)&pEO,  g_EO);
    cudaGetSymbolAddress((void**)&ptw,  g_topk_w);
    cudaGetSymbolAddress((void**)&pids, g_topk_ids);
    cudaGetSymbolAddress((void**)&pcnt, g_counts);
    cudaGetSymbolAddress((void**)&ptok, g_ex_tok);
    cudaGetSymbolAddress((void**)&ppair, g_ex_pair);

    cudaFuncSetAttribute(wm_gemm_kernel,
                         cudaFuncAttributeMaxDynamicSharedMemorySize, GEMM_SMEM);
    cudaFuncSetAttribute(fused_gu_kernel,
                         cudaFuncAttributeMaxDynamicSharedMemorySize, GEMM_SMEM);

    // side stream + fork/join events (host-side objects; no device alloc)
    cudaStream_t s2;
    cudaStreamCreateWithFlags(&s2, cudaStreamNonBlocking);
    cudaEvent_t evFork, evJoin;
    cudaEventCreateWithFlags(&evFork, cudaEventDisableTiming);
    cudaEventCreateWithFlags(&evJoin, cudaEventDisableTiming);

    // 0) x -> fp16 hi/lo (needed by BOTH chains)
    cvt_x_kernel<<<512, 256>>>(x, pxh, pxl, T_TOK * H_DIM / 2);
    cudaEventRecord(evFork, 0);
    cudaStreamWaitEvent(s2, evFork, 0);

    // ---- shared-expert chain on s2 (independent of routing) ----
    fused_gu_kernel<<<dim3(NSI / 64, 4, 1), 256, GEMM_SMEM, s2>>>(
        pxh, pxl, swgu, pASh, pASl, T_TOK, nullptr, H_DIM / 16, H_DIM, NSI2, NSI,
        0, nullptr, nullptr);
    wm_gemm_kernel<<<dim3(H_DIM / 128, 4, 1), 256, GEMM_SMEM, s2>>>(
        pASh, pASl, swdn, out, T_TOK, nullptr, NSI / 16, NSI, H_DIM, H_DIM,
        0, nullptr, nullptr);
    cudaEventRecord(evJoin, s2);

    // ---- routed chain on the capture stream ----
    router_kernel<<<16, 256>>>(x, gate_w, cbias, pids, ptw);
    build_lists_kernel<<<1, 1024>>>(pids, pcnt, ptok, ppair);
    fused_gu_kernel<<<dim3(I_DIM / 64, 4, N_EXP), 256, GEMM_SMEM>>>(
        pxh, pxl, w13, pA1h, pA1l, 0, pcnt, H_DIM / 16, H_DIM, I2_DIM, I_DIM,
        (size_t)H_DIM * I2_DIM, ptok, ppair);
    wm_gemm_kernel<<<dim3(H_DIM / 128, 4, N_EXP), 256, GEMM_SMEM>>>(
        pA1h, pA1l, w2, pEO, 0, pcnt, I_DIM / 16, I_DIM, H_DIM, H_DIM,
        (size_t)I_DIM * H_DIM, ppair, ppair);

    // ---- join: combine needs EO (routed) and out (shared) ----
    cudaStreamWaitEvent(0, evJoin, 0);
    combine_kernel<<<T_TOK, 256>>>(pEO, ptw, out);
}

// round 17
// speedup vs baseline: 2.0778x; 1.1820x over previous
#include <cuda_runtime.h>
#include <cstdint>
#include <math.h>

typedef unsigned long long u64;
typedef unsigned short u16;

// ---------------- problem constants ----------------
#define T_TOK 512
#define H_DIM 2048
#define N_EXP 32
#define N_GRP 8
#define TOPK_GRP 4
#define TOP_K 6
#define I_DIM 1408
#define I2_DIM 2816
#define NSI 2816
#define NSI2 5632
#define SCALE_F 2.5f
#define MAXM 512
#define NPAIR (T_TOK * TOP_K)   // 3072

// ---------------- scratch (static device memory; no allocation) ----------------
__device__ u16   g_xh[T_TOK * H_DIM];      // x hi fp16
__device__ u16   g_xl[T_TOK * H_DIM];      // x lo fp16
__device__ u16   g_A1h[NPAIR * I_DIM];     // routed act hi
__device__ u16   g_A1l[NPAIR * I_DIM];     // routed act lo
__device__ u16   g_ASh[T_TOK * NSI];       // shared act hi
__device__ u16   g_ASl[T_TOK * NSI];       // shared act lo
__device__ float g_EO[NPAIR * H_DIM];      // per-pair expert output
__device__ int   g_topk_ids[NPAIR];
__device__ float g_topk_w[NPAIR];
__device__ int   g_counts[N_EXP];
__device__ int   g_ex_tok[N_EXP * MAXM];
__device__ int   g_ex_pair[N_EXP * MAXM];

// ---------------- helpers ----------------
__device__ __forceinline__ uint32_t smem_u32(const void* p) {
    uint32_t a;
    asm("{ .reg .u64 t; cvta.to.shared.u64 t, %1; cvt.u32.u64 %0, t; }" : "=r"(a) : "l"(p));
    return a;
}
__device__ __forceinline__ uint32_t h2pack(float x0, float x1) {
    uint32_t r;
    asm("cvt.rn.f16x2.f32 %0, %1, %2;" : "=r"(r) : "f"(x1), "f"(x0));
    return r;
}
__device__ __forceinline__ uint32_t l2pack(float x0, float x1, uint32_t h) {
    float h0, h1;
    asm("{ .reg .f16 a, b; mov.b32 {a, b}, %2; cvt.f32.f16 %0, a; cvt.f32.f16 %1, b; }"
        : "=f"(h0), "=f"(h1) : "r"(h));
    return h2pack(x0 - h0, x1 - h1);
}

#define LDM_X4(r, a) \
    asm volatile("ldmatrix.sync.aligned.m8n8.x4.shared.b16 {%0,%1,%2,%3}, [%4];" \
        : "=r"((r)[0]), "=r"((r)[1]), "=r"((r)[2]), "=r"((r)[3]) : "r"(a))

#define MMA16816(d, a, b0v, b1v) \
    asm volatile("mma.sync.aligned.m16n8k16.row.col.f32.f16.f16.f32 " \
        "{%0,%1,%2,%3}, {%4,%5,%6,%7}, {%8,%9}, {%0,%1,%2,%3};" \
        : "+f"((d)[0]), "+f"((d)[1]), "+f"((d)[2]), "+f"((d)[3]) \
        : "r"((a)[0]), "r"((a)[1]), "r"((a)[2]), "r"((a)[3]), "r"(b0v), "r"(b1v))

#define STS128(addr, v) \
    asm volatile("st.shared.v4.b32 [%0], {%1, %2, %3, %4};" \
        :: "r"(addr), "r"((v).x), "r"((v).y), "r"((v).z), "r"((v).w) : "memory")

// smem layout (BK=16): row stride 48B, 128 rows per matrix
#define ROWB 48
#define OFF_AH 0
#define OFF_AL 6144
#define OFF_BH 12288
#define OFF_BL 18432
#define BUF_BYTES 24576
#define GEMM_SMEM (2 * BUF_BYTES)   // 48 KB -> 2 CTAs/SM

// convert 8 floats -> hi/lo f16x4 and store (weights / B side only)
__device__ __forceinline__ void cvt_store8(uint32_t sb_h, uint32_t sb_l, const float* f) {
    uint4 h, l;
    h.x = h2pack(f[0], f[1]); h.y = h2pack(f[2], f[3]);
    h.z = h2pack(f[4], f[5]); h.w = h2pack(f[6], f[7]);
    l.x = l2pack(f[0], f[1], h.x); l.y = l2pack(f[2], f[3], h.y);
    l.z = l2pack(f[4], f[5], h.z); l.w = l2pack(f[6], f[7], h.w);
    STS128(sb_h, h);
    STS128(sb_l, l);
}

// ---------------- x fp32 -> fp16 hi/lo pre-pass ----------------
__global__ void __launch_bounds__(256) cvt_x_kernel(
    const float* __restrict__ x, u16* __restrict__ xh, u16* __restrict__ xl, int n2)
{
    for (int i = blockIdx.x * blockDim.x + threadIdx.x; i < n2;
         i += gridDim.x * blockDim.x) {
        float v0 = x[2 * i], v1 = x[2 * i + 1];
        uint32_t h = h2pack(v0, v1);
        uint32_t l = l2pack(v0, v1, h);
        ((uint32_t*)xh)[i] = h;
        ((uint32_t*)xl)[i] = l;
    }
}

// =====================================================================
// Plain GEMM (down proj): C[rowsC[m]] = A[rowsA[m]] @ (B + e*strideB)
// A is fp16 hi/lo; B fp32 converted inline.
// CTA 128x128, BK=16, 8 warps (2x4), warp 64x32, fp16-split x3 HMMA.
// =====================================================================
__global__ void __launch_bounds__(256, 2) wm_gemm_kernel(
    const u16* __restrict__ Ah, const u16* __restrict__ Al,
    const float* __restrict__ B, float* __restrict__ C,
    int Mfixed, const int* __restrict__ Mcnt,
    int nkt, int lda, int ldb, int ldc, size_t strideB,
    const int* __restrict__ rowsA, const int* __restrict__ rowsC)
{
    extern __shared__ char sm_raw[];
    int e = blockIdx.z;
    int M = Mcnt ? Mcnt[e] : Mfixed;
    int m0 = blockIdx.y * 128;
    if (m0 >= M) return;
    int n0 = blockIdx.x * 128;

    uint32_t smem0 = smem_u32(sm_raw);
    int tid = threadIdx.x;
    int wid = tid >> 5, lane = tid & 31;
    int wm = (wid >> 2) * 64, wn = (wid & 3) * 32;

    // A producer: row = tid>>1, 8 halves at (tid&1)*8
    int prow = tid >> 1;
    int phalf = tid & 1;
    int mg = m0 + prow; if (mg > M - 1) mg = M - 1;
    int arow = rowsA ? rowsA[e * MAXM + mg] : mg;
    const u16* Ahp = Ah + (size_t)arow * lda + phalf * 8;
    const u16* Alp = Al + (size_t)arow * lda + phalf * 8;
    uint32_t aoff = (uint32_t)(prow * ROWB + phalf * 16);
    // B producer: n = tid&127, 8 k at (tid>>7)*8 (transpose into smem)
    int bn = tid & 127;
    int bkh = tid >> 7;
    const float* Bp = B + (size_t)e * strideB + (size_t)(bkh * 8) * ldb + n0 + bn;
    uint32_t boff = (uint32_t)(bn * ROWB + bkh * 16);

    uint32_t a_lm = (uint32_t)((wm + (lane & 15)) * ROWB + (lane >> 4) * 16);
    uint32_t b_lm = (uint32_t)((wn + (lane & 15)) * ROWB + (lane >> 4) * 16);

    float acc[4][4][4];
    #pragma unroll
    for (int i = 0; i < 4; i++)
        #pragma unroll
        for (int j = 0; j < 4; j++)
            #pragma unroll
            for (int q = 0; q < 4; q++) acc[i][j][q] = 0.f;

    uint4 arh, arl;
    float br[8];
    {
        arh = *(const uint4*)Ahp;
        arl = *(const uint4*)Alp;
        #pragma unroll
        for (int j = 0; j < 8; j++) br[j] = Bp[(size_t)j * ldb];
        STS128(smem0 + OFF_AH + aoff, arh);
        STS128(smem0 + OFF_AL + aoff, arl);
        cvt_store8(smem0 + OFF_BH + boff, smem0 + OFF_BL + boff, br);
    }
    __syncthreads();

    for (int kt = 0; kt < nkt; kt++) {
        int buf = kt & 1;
        bool more = (kt + 1 < nkt);
        if (more) {
            Ahp += 16; Alp += 16; Bp += (size_t)16 * ldb;
            arh = *(const uint4*)Ahp;
            arl = *(const uint4*)Alp;
            #pragma unroll
            for (int j = 0; j < 8; j++) br[j] = Bp[(size_t)j * ldb];
        }

        uint32_t base = smem0 + buf * BUF_BYTES;
        uint32_t ah[4][4];
        #pragma unroll
        for (int mf = 0; mf < 4; mf++)
            LDM_X4(ah[mf], base + OFF_AH + a_lm + mf * (16 * ROWB));
        uint32_t bh[2][4], bl[2][4];
        #pragma unroll
        for (int nq = 0; nq < 2; nq++) {
            uint32_t bd = base + OFF_BH + b_lm + nq * (16 * ROWB);
            LDM_X4(bh[nq], bd);
            LDM_X4(bl[nq], bd + (OFF_BL - OFF_BH));
        }
        // p0: Ah*Bh ; p1: Ah*Bl  (16 independent accs between reuse)
        #pragma unroll
        for (int mf = 0; mf < 4; mf++)
            #pragma unroll
            for (int nf = 0; nf < 4; nf++) {
                int nq = nf >> 1, sel = nf & 1;
                MMA16816(acc[mf][nf], ah[mf], bh[nq][sel], bh[nq][sel + 2]);
            }
        #pragma unroll
        for (int mf = 0; mf < 4; mf++)
            #pragma unroll
            for (int nf = 0; nf < 4; nf++) {
                int nq = nf >> 1, sel = nf & 1;
                MMA16816(acc[mf][nf], ah[mf], bl[nq][sel], bl[nq][sel + 2]);
            }
        // p2: Al*Bh (load Al late to shorten live ranges)
        uint32_t al[4][4];
        #pragma unroll
        for (int mf = 0; mf < 4; mf++)
            LDM_X4(al[mf], base + OFF_AL + a_lm + mf * (16 * ROWB));
        #pragma unroll
        for (int mf = 0; mf < 4; mf++)
            #pragma unroll
            for (int nf = 0; nf < 4; nf++) {
                int nq = nf >> 1, sel = nf & 1;
                MMA16816(acc[mf][nf], al[mf], bh[nq][sel], bh[nq][sel + 2]);
            }

        if (more) {
            uint32_t sb = smem0 + (buf ^ 1) * BUF_BYTES;
            STS128(sb + OFF_AH + aoff, arh);
            STS128(sb + OFF_AL + aoff, arl);
            cvt_store8(sb + OFF_BH + boff, sb + OFF_BL + boff, br);
        }
        __syncthreads();
    }

    #pragma unroll
    for (int mf = 0; mf < 4; mf++) {
        int rbase = m0 + wm + mf * 16 + (lane >> 2);
        #pragma unroll
        for (int half = 0; half < 2; half++) {
            int mm = rbase + half * 8;
            if (mm < M) {
                int crow = rowsC ? rowsC[e * MAXM + mm] : mm;
                float* cp = C + (size_t)crow * ldc + n0 + wn + (lane & 3) * 2;
                #pragma unroll
                for (int nf = 0; nf < 4; nf++) {
                    float2 v;
                    v.x = acc[mf][nf][half * 2];
                    v.y = acc[mf][nf][half * 2 + 1];
                    *(float2*)(cp + nf * 8) = v;
                }
            }
        }
    }
}

// =====================================================================
// Fused gate/up GEMM + SiLU; A fp16 hi/lo in, ACT fp16 hi/lo out.
// CTA 128m x (64 gate + 64 up); warp 64m x 16n per half.
// =====================================================================
__global__ void __launch_bounds__(256, 2) fused_gu_kernel(
    const u16* __restrict__ Ah, const u16* __restrict__ Al,
    const float* __restrict__ B,
    u16* __restrict__ ACTh, u16* __restrict__ ACTl,
    int Mfixed, const int* __restrict__ Mcnt,
    int nkt, int lda, int ldb, int halfN, size_t strideB,
    const int* __restrict__ rowsA, const int* __restrict__ rowsC)
{
    extern __shared__ char sm_raw[];
    int e = blockIdx.z;
    int M = Mcnt ? Mcnt[e] : Mfixed;
    int m0 = blockIdx.y * 128;
    if (m0 >= M) return;
    int n0 = blockIdx.x * 64;

    uint32_t smem0 = smem_u32(sm_raw);
    int tid = threadIdx.x;
    int wid = tid >> 5, lane = tid & 31;
    int wm = (wid >> 2) * 64, wn = (wid & 3) * 16;

    int prow = tid >> 1;
    int phalf = tid & 1;
    int mg = m0 + prow; if (mg > M - 1) mg = M - 1;
    int arow = rowsA ? rowsA[e * MAXM + mg] : mg;
    const u16* Ahp = Ah + (size_t)arow * lda + phalf * 8;
    const u16* Alp = Al + (size_t)arow * lda + phalf * 8;
    uint32_t aoff = (uint32_t)(prow * ROWB + phalf * 16);
    // B producer: col = tid&127 (0-63 gate, 64-127 up), 8 k at (tid>>7)*8
    int col = tid & 127;
    int bkh = tid >> 7;
    int gcol = n0 + (col & 63) + (col >> 6) * halfN;
    const float* Bp = B + (size_t)e * strideB + (size_t)(bkh * 8) * ldb + gcol;
    uint32_t boff = (uint32_t)(col * ROWB + bkh * 16);

    uint32_t a_lm = (uint32_t)((wm + (lane & 15)) * ROWB + (lane >> 4) * 16);
    uint32_t b_lm0 = (uint32_t)((wn + (lane & 15)) * ROWB + (lane >> 4) * 16);

    float acc[4][2][2][4];
    #pragma unroll
    for (int i = 0; i < 4; i++)
        #pragma unroll
        for (int h = 0; h < 2; h++)
            #pragma unroll
            for (int j = 0; j < 2; j++)
                #pragma unroll
                for (int q = 0; q < 4; q++) acc[i][h][j][q] = 0.f;

    uint4 arh, arl;
    float br[8];
    {
        arh = *(const uint4*)Ahp;
        arl = *(const uint4*)Alp;
        #pragma unroll
        for (int j = 0; j < 8; j++) br[j] = Bp[(size_t)j * ldb];
        STS128(smem0 + OFF_AH + aoff, arh);
        STS128(smem0 + OFF_AL + aoff, arl);
        cvt_store8(smem0 + OFF_BH + boff, smem0 + OFF_BL + boff, br);
    }
    __syncthreads();

    for (int kt = 0; kt < nkt; kt++) {
        int buf = kt & 1;
        bool more = (kt + 1 < nkt);
        if (more) {
            Ahp += 16; Alp += 16; Bp += (size_t)16 * ldb;
            arh = *(const uint4*)Ahp;
            arl = *(const uint4*)Alp;
            #pragma unroll
            for (int j = 0; j < 8; j++) br[j] = Bp[(size_t)j * ldb];
        }

        uint32_t base = smem0 + buf * BUF_BYTES;
        uint32_t ah[4][4], al[4][4];
        #pragma unroll
        for (int mf = 0; mf < 4; mf++) {
            uint32_t ad = base + OFF_AH + a_lm + mf * (16 * ROWB);
            LDM_X4(ah[mf], ad);
            LDM_X4(al[mf], ad + (OFF_AL - OFF_AH));
        }
        #pragma unroll
        for (int h = 0; h < 2; h++) {
            uint32_t bd = base + OFF_BH + b_lm0 + h * (64 * ROWB);
            uint32_t bh[4], bl[4];
            LDM_X4(bh, bd);
            LDM_X4(bl, bd + (OFF_BL - OFF_BH));
            #pragma unroll
            for (int mf = 0; mf < 4; mf++)
                #pragma unroll
                for (int nf = 0; nf < 2; nf++)
                    MMA16816(acc[mf][h][nf], ah[mf], bh[nf], bh[nf + 2]);
            #pragma unroll
            for (int mf = 0; mf < 4; mf++)
                #pragma unroll
                for (int nf = 0; nf < 2; nf++)
                    MMA16816(acc[mf][h][nf], ah[mf], bl[nf], bl[nf + 2]);
            #pragma unroll
            for (int mf = 0; mf < 4; mf++)
                #pragma unroll
                for (int nf = 0; nf < 2; nf++)
                    MMA16816(acc[mf][h][nf], al[mf], bh[nf], bh[nf + 2]);
        }

        if (more) {
            uint32_t sb = smem0 + (buf ^ 1) * BUF_BYTES;
            STS128(sb + OFF_AH + aoff, arh);
            STS128(sb + OFF_AL + aoff, arl);
            cvt_store8(sb + OFF_BH + boff, sb + OFF_BL + boff, br);
        }
        __syncthreads();
    }

    // epilogue: act = silu(gate) * up -> fp16 hi/lo rows (gathered)
    #pragma unroll
    for (int mf = 0; mf < 4; mf++) {
        int rbase = m0 + wm + mf * 16 + (lane >> 2);
        #pragma unroll
        for (int half = 0; half < 2; half++) {
            int mm = rbase + half * 8;
            if (mm < M) {
                int crow = rowsC ? rowsC[e * MAXM + mm] : mm;
                size_t rowoff = (size_t)crow * halfN + n0 + wn + (lane & 3) * 2;
                #pragma unroll
                for (int nf = 0; nf < 2; nf++) {
                    float g0v = acc[mf][0][nf][half * 2];
                    float g1v = acc[mf][0][nf][half * 2 + 1];
                    float u0v = acc[mf][1][nf][half * 2];
                    float u1v = acc[mf][1][nf][half * 2 + 1];
                    float a0 = (g0v / (1.f + expf(-g0v))) * u0v;
                    float a1 = (g1v / (1.f + expf(-g1v))) * u1v;
                    uint32_t hx = h2pack(a0, a1);
                    uint32_t lx = l2pack(a0, a1, hx);
                    *(uint32_t*)(ACTh + rowoff + nf * 8) = hx;
                    *(uint32_t*)(ACTl + rowoff + nf * 8) = lx;
                }
            }
        }
    }
}

// ---------------- router: H-split logits + sigmoid + grouped topk ----------
// 128 blocks x 256 threads; block = 4 tokens. Warp w covers h-chunk
// [w*256, w*256+256); partials reduced via smem; warp 0 does topk.
__global__ void __launch_bounds__(256) router_kernel(
    const float* __restrict__ x, const float* __restrict__ gw,
    const float* __restrict__ bias, int* __restrict__ ids, float* __restrict__ tw)
{
    __shared__ float part[8][4][32];
    const unsigned FULL = 0xffffffffu;
    int warp = threadIdx.x >> 5, lane = threadIdx.x & 31;
    int t0 = blockIdx.x * 4;
    const float* xr = x + (size_t)t0 * H_DIM;

    float acc0 = 0.f, acc1 = 0.f, acc2 = 0.f, acc3 = 0.f;
    int h0 = warp * 256;
    #pragma unroll 4
    for (int h = h0; h < h0 + 256; h++) {
        float g = gw[h * N_EXP + lane];
        acc0 += xr[h] * g;
        acc1 += xr[H_DIM + h] * g;
        acc2 += xr[2 * H_DIM + h] * g;
        acc3 += xr[3 * H_DIM + h] * g;
    }
    part[warp][0][lane] = acc0;
    part[warp][1][lane] = acc1;
    part[warp][2][lane] = acc2;
    part[warp][3][lane] = acc3;
    __syncthreads();

    if (warp == 0) {
        float b = bias[lane];
        for (int tt = 0; tt < 4; tt++) {
            int t = t0 + tt;
            float logit = 0.f;
            #pragma unroll
            for (int w = 0; w < 8; w++) logit += part[w][tt][lane];

            float s   = 1.f / (1.f + expf(-logit));
            float sfc = s + b;

            float a  = sfc;
            float bb = __shfl_xor_sync(FULL, a, 1);
            float hi = fmaxf(a, bb), lo = fminf(a, bb);
            float hi2 = __shfl_xor_sync(FULL, hi, 2);
            float lo2 = __shfl_xor_sync(FULL, lo, 2);
            float top1   = fmaxf(hi, hi2);
            float second = fmaxf(fminf(hi, hi2), fmaxf(lo, lo2));
            float gscore = top1 + second;
            int gid = lane >> 2;

            int grank = 0;
            #pragma unroll
            for (int j = 0; j < N_GRP; j++) {
                float gj = __shfl_sync(FULL, gscore, j * 4);
                grank += (gj > gscore) || (gj == gscore && j < gid);
            }
            float masked = (grank < TOPK_GRP) ? sfc : -INFINITY;

            int rank = 0;
            #pragma unroll
            for (int j = 0; j < 32; j++) {
                float vj = __shfl_sync(FULL, masked, j);
                rank += (vj > masked) || (vj == masked && j < lane);
            }
            bool sel = rank < TOP_K;

            float wsum = sel ? s : 0.f;
            #pragma unroll
            for (int off = 16; off; off >>= 1) wsum += __shfl_xor_sync(FULL, wsum, off);

            if (sel) {
                ids[t * TOP_K + rank] = lane;
                tw[t * TOP_K + rank]  = s / wsum * SCALE_F;
            }
        }
    }
}

// ---------------- deterministic expert->token compaction ----------------
__global__ void __launch_bounds__(1024) build_lists_kernel(
    const int* __restrict__ ids, int* __restrict__ counts,
    int* __restrict__ ex_tok, int* __restrict__ ex_pair)
{
    const unsigned FULL = 0xffffffffu;
    int e = threadIdx.x >> 5;
    int lane = threadIdx.x & 31;
    int t0 = lane * 16;

    int cnt = 0;
    for (int t = t0; t < t0 + 16; t++)
        #pragma unroll
        for (int k = 0; k < TOP_K; k++)
            if (ids[t * TOP_K + k] == e) cnt++;

    int off = cnt;
    #pragma unroll
    for (int d = 1; d < 32; d <<= 1) {
        int v = __shfl_up_sync(FULL, off, d);
        if (lane >= d) off += v;
    }
    int total = __shfl_sync(FULL, off, 31);
    off -= cnt;

    for (int t = t0; t < t0 + 16; t++)
        #pragma unroll
        for (int k = 0; k < TOP_K; k++)
            if (ids[t * TOP_K + k] == e) {
                ex_tok[e * MAXM + off]  = t;
                ex_pair[e * MAXM + off] = t * TOP_K + k;
                off++;
            }
    if (lane == 0) counts[e] = total;
}

// ---------------- combine: out[t] += sum_k w[t,k] * EO[t*6+k] ----------------
__global__ void __launch_bounds__(256) combine_kernel(
    const float* __restrict__ EO, const float* __restrict__ tw, float* __restrict__ out)
{
    int t = blockIdx.x;
    const float* w = tw + t * TOP_K;
    float w0 = w[0], w1 = w[1], w2v = w[2], w3 = w[3], w4 = w[4], w5 = w[5];
    const float* eb = EO + (size_t)t * TOP_K * H_DIM;
    float* orow = out + (size_t)t * H_DIM;
    for (int c = threadIdx.x; c < H_DIM; c += blockDim.x) {
        float v = orow[c];
        v += w0  * eb[c]
           + w1  * eb[H_DIM + c]
           + w2v * eb[2 * H_DIM + c]
           + w3  * eb[3 * H_DIM + c]
           + w4  * eb[4 * H_DIM + c]
           + w5  * eb[5 * H_DIM + c];
        orow[c] = v;
    }
}

// ---------------- launch (forked graph: shared chain || routed chain) ------
extern "C" void kernel_launch(void* const* d_in, const int* in_sizes, int n_in,
                              void* d_out, int out_size)
{
    (void)in_sizes; (void)n_in; (void)out_size;
    const float* x      = (const float*)d_in[0];
    const float* gate_w = (const float*)d_in[2];
    const float* cbias  = (const float*)d_in[3];
    const float* w13    = (const float*)d_in[4];
    const float* w2     = (const float*)d_in[5];
    const float* swgu   = (const float*)d_in[6];
    const float* swdn   = (const float*)d_in[7];
    float* out = (float*)d_out;

    float *pEO, *ptw;
    u16 *pxh, *pxl, *pA1h, *pA1l, *pASh, *pASl;
    int *pids, *pcnt, *ptok, *ppair;
    cudaGetSymbolAddress((void**)&pxh,  g_xh);
    cudaGetSymbolAddress((void**)&pxl,  g_xl);
    cudaGetSymbolAddress((void**)&pA1h, g_A1h);
    cudaGetSymbolAddress((void**)&pA1l, g_A1l);
    cudaGetSymbolAddress((void**)&pASh, g_ASh);
    cudaGetSymbolAddress((void**)&pASl, g_ASl);
    cudaGetSymbolAddress((void**)&pEO,  g_EO);
    cudaGetSymbolAddress((void**)&ptw,  g_topk_w);
    cudaGetSymbolAddress((void**)&pids, g_topk_ids);
    cudaGetSymbolAddress((void**)&pcnt, g_counts);
    cudaGetSymbolAddress((void**)&ptok, g_ex_tok);
    cudaGetSymbolAddress((void**)&ppair, g_ex_pair);

    cudaFuncSetAttribute(wm_gemm_kernel,
                         cudaFuncAttributeMaxDynamicSharedMemorySize, GEMM_SMEM);
    cudaFuncSetAttribute(fused_gu_kernel,
                         cudaFuncAttributeMaxDynamicSharedMemorySize, GEMM_SMEM);

    // side stream + fork/join events (host-side objects; no device alloc)
    cudaStream_t s2;
    cudaStreamCreateWithFlags(&s2, cudaStreamNonBlocking);
    cudaEvent_t evFork, evCvt, evJoin;
    cudaEventCreateWithFlags(&evFork, cudaEventDisableTiming);
    cudaEventCreateWithFlags(&evCvt,  cudaEventDisableTiming);
    cudaEventCreateWithFlags(&evJoin, cudaEventDisableTiming);

    // fork: s2 starts from the same point (beginning of capture)
    cudaEventRecord(evFork, 0);
    cudaStreamWaitEvent(s2, evFork, 0);

    // ---- s2: cvt_x, then shared-expert chain (independent of routing) ----
    cvt_x_kernel<<<512, 256, 0, s2>>>(x, pxh, pxl, T_TOK * H_DIM / 2);
    cudaEventRecord(evCvt, s2);
    fused_gu_kernel<<<dim3(NSI / 64, 4, 1), 256, GEMM_SMEM, s2>>>(
        pxh, pxl, swgu, pASh, pASl, T_TOK, nullptr, H_DIM / 16, H_DIM, NSI2, NSI,
        0, nullptr, nullptr);
    wm_gemm_kernel<<<dim3(H_DIM / 128, 4, 1), 256, GEMM_SMEM, s2>>>(
        pASh, pASl, swdn, out, T_TOK, nullptr, NSI / 16, NSI, H_DIM, H_DIM,
        0, nullptr, nullptr);
    cudaEventRecord(evJoin, s2);

    // ---- main stream: router + lists overlap with cvt_x ----
    router_kernel<<<128, 256>>>(x, gate_w, cbias, pids, ptw);
    build_lists_kernel<<<1, 1024>>>(pids, pcnt, ptok, ppair);
    cudaStreamWaitEvent(0, evCvt, 0);   // routed GEMMs need xh/xl
    fused_gu_kernel<<<dim3(I_DIM / 64, 4, N_EXP), 256, GEMM_SMEM>>>(
        pxh, pxl, w13, pA1h, pA1l, 0, pcnt, H_DIM / 16, H_DIM, I2_DIM, I_DIM,
        (size_t)H_DIM * I2_DIM, ptok, ppair);
    wm_gemm_kernel<<<dim3(H_DIM / 128, 4, N_EXP), 256, GEMM_SMEM>>>(
        pA1h, pA1l, w2, pEO, 0, pcnt, I_DIM / 16, I_DIM, H_DIM, H_DIM,
        (size_t)I_DIM * H_DIM, ppair, ppair);

    // ---- join: combine needs EO (routed) and out (shared) ----
    cudaStreamWaitEvent(0, evJoin, 0);
    combine_kernel<<<T_TOK, 256>>>(pEO, ptw, out);
}